// round 6
// baseline (speedup 1.0000x reference)
#include <cuda_runtime.h>
#include <cstdint>

#define B_IMG 128
#define B_CAP 128
#define R 64
#define W 64
#define D 128

#define A_PITCH 144            // g*144 mod 32 = {0,16} -> conflict-free LDS.128 frags
#define S_PITCH 65             // stride 1 across threads -> conflict-free rows AND cols
#define TILE_F  (64 * A_PITCH) // 9216 floats per operand tile
#define SS_F    (64 * S_PITCH) // 4160 floats per sims tile (2 overlay into As: 8320<=9216)

#define SMEM_FLOATS (3 * TILE_F + 256)
#define SMEM_BYTES  (SMEM_FLOATS * 4)   // 111,616 B -> 2 CTAs/SM (223 KB < 228 KB)

__device__ __forceinline__ uint32_t f2tf32(float x) {
    uint32_t r;
    asm("cvt.rna.tf32.f32 %0, %1;" : "=r"(r) : "f"(x));
    return r;
}

#define MMA_TF32(d, a0, a1, a2, a3, b0, b1)                                   \
    asm volatile(                                                             \
        "mma.sync.aligned.m16n8k8.row.col.f32.tf32.tf32.f32 "                 \
        "{%0,%1,%2,%3}, {%4,%5,%6,%7}, {%8,%9}, {%0,%1,%2,%3};\n"             \
        : "+f"(d[0]), "+f"(d[1]), "+f"(d[2]), "+f"(d[3])                      \
        : "r"(a0), "r"(a1), "r"(a2), "r"(a3), "r"(b0), "r"(b1))

// One CTA = 1 image x 2 captions. 256 threads.
// Operand tiles use a permuted K layout: within each 16-col group, column c is
// stored at position (c&3)*4 + (c>>2), so a thread's 4 values for two k-steps
// (cols t4, t4+4, t4+8, t4+12) are one aligned float4.
__global__ __launch_bounds__(256) void select_kernel(
    const float* __restrict__ imgs, const float* __restrict__ caps,
    const int* __restrict__ img_lens, const int* __restrict__ cap_lens,
    float* __restrict__ out)
{
    extern __shared__ float sm[];
    float* As  = sm;                    // [64][A_PITCH] tf32 imgs tile (permuted K)
    float* Bs0 = sm + TILE_F;           // caps tile pair 0 (pair 1 at +TILE_F)
    float* red = sm + 3 * TILE_F;       // [256]

    const int i   = blockIdx.y;
    const int t0  = blockIdx.x * 2;
    const int tid = threadIdx.x;

    const int nv  = __ldg(img_lens + i);
    const int nt0 = __ldg(cap_lens + t0);
    const int nt1 = __ldg(cap_lens + t0 + 1);

    // ---- Phase 1: gather-load + tf32-convert into permuted smem ----
    // quad-task j: row = j>>5, group = (j>>2)&7, t4 = j&3
    // loads gmem cols group*16 + t4 + {0,4,8,12}; stores one float4 at
    // row*A_PITCH + group*16 + t4*4.
    {
        const float* gi = imgs + (size_t)i * R * D;
        const float* gc = caps + (size_t)t0 * W * D;
        #pragma unroll
        for (int j = tid; j < R * D / 4; j += 256) {
            int row = j >> 5, grp = (j >> 2) & 7, t4 = j & 3;
            const float* g = gi + row * D + grp * 16 + t4;
            float4 w;
            w.x = __uint_as_float(f2tf32(g[0]));
            w.y = __uint_as_float(f2tf32(g[4]));
            w.z = __uint_as_float(f2tf32(g[8]));
            w.w = __uint_as_float(f2tf32(g[12]));
            *(float4*)(As + row * A_PITCH + grp * 16 + t4 * 4) = w;
        }
        #pragma unroll
        for (int j = tid; j < 2 * W * D / 4; j += 256) {
            int p = j >> 11;
            int jj = j & 2047;
            int row = jj >> 5, grp = (jj >> 2) & 7, t4 = jj & 3;
            const float* g = gc + p * W * D + row * D + grp * 16 + t4;
            float4 w;
            w.x = __uint_as_float(f2tf32(g[0]));
            w.y = __uint_as_float(f2tf32(g[4]));
            w.z = __uint_as_float(f2tf32(g[8]));
            w.w = __uint_as_float(f2tf32(g[12]));
            *(float4*)(Bs0 + p * TILE_F + row * A_PITCH + grp * 16 + t4 * 4) = w;
        }
    }
    __syncthreads();

    // ---- Phase 2: per pair 64x64x128 GEMM, LDS.128 frag loads ----
    {
        const int warp = tid >> 5;
        const int lane = tid & 31;
        const int p    = warp >> 2;
        const int w4   = warp & 3;
        const int g    = lane >> 2;
        const int t4   = lane & 3;
        const int warpM = (w4 >> 1) * 32;
        const int warpN = (w4 & 1) * 32;
        const float* Bp = Bs0 + p * TILE_F;
        const int   ntp = p ? nt1 : nt0;

        float acc[2][4][4];
        #pragma unroll
        for (int mi = 0; mi < 2; ++mi)
            #pragma unroll
            for (int ni = 0; ni < 4; ++ni)
                #pragma unroll
                for (int q = 0; q < 4; ++q) acc[mi][ni][q] = 0.0f;

        #pragma unroll
        for (int grp = 0; grp < 8; ++grp) {       // 16 K columns per group
            const int off = grp * 16 + t4 * 4;
            float4 aq0[2], aq8[2], bq[4];
            #pragma unroll
            for (int mi = 0; mi < 2; ++mi) {
                const float* ap = As + (warpM + mi * 16 + g) * A_PITCH + off;
                aq0[mi] = *(const float4*)ap;                 // row g
                aq8[mi] = *(const float4*)(ap + 8 * A_PITCH); // row g+8
            }
            #pragma unroll
            for (int ni = 0; ni < 4; ++ni)
                bq[ni] = *(const float4*)(Bp + (warpN + ni * 8 + g) * A_PITCH + off);

            // k-step 0: cols t4, t4+4  -> .x, .y
            #pragma unroll
            for (int mi = 0; mi < 2; ++mi)
                #pragma unroll
                for (int ni = 0; ni < 4; ++ni)
                    MMA_TF32(acc[mi][ni],
                             __float_as_uint(aq0[mi].x), __float_as_uint(aq8[mi].x),
                             __float_as_uint(aq0[mi].y), __float_as_uint(aq8[mi].y),
                             __float_as_uint(bq[ni].x),  __float_as_uint(bq[ni].y));
            // k-step 1: cols t4+8, t4+12 -> .z, .w
            #pragma unroll
            for (int mi = 0; mi < 2; ++mi)
                #pragma unroll
                for (int ni = 0; ni < 4; ++ni)
                    MMA_TF32(acc[mi][ni],
                             __float_as_uint(aq0[mi].z), __float_as_uint(aq8[mi].z),
                             __float_as_uint(aq0[mi].w), __float_as_uint(aq8[mi].w),
                             __float_as_uint(bq[ni].z),  __float_as_uint(bq[ni].w));
        }

        __syncthreads();   // all warps done reading As/Bs; Ss overlays As

        // epilogue: store PRE-SHIFTED sims z' = sims + 256 (masked -> exactly 255)
        float* Sp = sm + p * SS_F;
        #pragma unroll
        for (int mi = 0; mi < 2; ++mi) {
            #pragma unroll
            for (int ni = 0; ni < 4; ++ni) {
                int r0 = warpM + mi * 16 + g;
                int r1 = r0 + 8;
                int c0 = warpN + ni * 8 + 2 * t4;
                bool cv0 = (c0 < ntp), cv1 = (c0 + 1 < ntp);
                Sp[r0 * S_PITCH + c0]     = (r0 < nv && cv0) ? acc[mi][ni][0] + 256.0f : 255.0f;
                Sp[r0 * S_PITCH + c0 + 1] = (r0 < nv && cv1) ? acc[mi][ni][1] + 256.0f : 255.0f;
                Sp[r1 * S_PITCH + c0]     = (r1 < nv && cv0) ? acc[mi][ni][2] + 256.0f : 255.0f;
                Sp[r1 * S_PITCH + c0 + 1] = (r1 < nv && cv1) ? acc[mi][ni][3] + 256.0f : 255.0f;
            }
        }
    }
    __syncthreads();

    // ---- Phase 3: sparsemax, shifted-accumulator Michelot (z already shifted) ----
    // tid layout: [pair(1)][role(1)][r(6)]; role 0 = region rows, role 1 = word cols
    {
        const int p    = tid >> 7;
        const int role = (tid >> 6) & 1;
        const int r    = tid & 63;
        const float* Sp = sm + p * SS_F;
        const int   ntp = p ? nt1 : nt0;
        const int   m   = role ? nv : ntp;      // valid elements in this line

        const float* bp = role ? (Sp + r) : (Sp + r * S_PITCH);
        const int   str = role ? S_PITCH : 1;

        float z[64];
        #pragma unroll
        for (int j = 0; j < 64; ++j) z[j] = bp[j * str];

        float s0 = 0.f, s1 = 0.f, s2 = 0.f, s3 = 0.f;
        #pragma unroll
        for (int j = 0; j < 64; j += 4) {
            s0 += z[j]; s1 += z[j + 1]; s2 += z[j + 2]; s3 += z[j + 3];
        }
        const float S = (s0 + s1) + (s2 + s3);

        // analytic init: support = valid set (masked entries sit at exactly 255)
        float kprev = (float)m;
        float tau = __fdividef(S - (float)(64 - m) * 255.0f - 1.0f, kprev);
        if (!(tau > 255.0f)) {                  // rare: true support includes masked
            tau = (S - 1.0f) * (1.0f / 64.0f);
            kprev = 64.0f;
        }

        // Michelot with joint sum+count accumulator: q = sum + 256*count
        float qf = kprev * tau + 1.0f;          // consistent q for the init tau
        float kf = kprev;
        #pragma unroll 1
        for (int it = 0; it < 24; ++it) {
            float q0 = 0.f, q1 = 0.f, q2 = 0.f, q3 = 0.f;
            #pragma unroll
            for (int j = 0; j < 64; j += 4) {
                if (z[j]     > tau) q0 += z[j];
                if (z[j + 1] > tau) q1 += z[j + 1];
                if (z[j + 2] > tau) q2 += z[j + 2];
                if (z[j + 3] > tau) q3 += z[j + 3];
            }
            qf = (q0 + q1) + (q2 + q3);
            kf = rintf(qf * 0.00390625f);       // exact count: |sum sims| <= 64 < 128
            if (kf == kprev) break;             // support stable -> tau is the fixpoint
            kprev = kf;
            tau = __fdividef(qf - 1.0f, kf);
        }

        // rsum = sum_active (z - tau)*z  [unshifted]
        //      = sum relu(z'-tau')^2 + (tau'-256) * sum relu(z'-tau')
        float a0 = 0.f, a1 = 0.f, a2 = 0.f, a3 = 0.f;
        #pragma unroll
        for (int j = 0; j < 64; j += 4) {
            float p0 = fmaxf(z[j]     - tau, 0.f);
            float p1 = fmaxf(z[j + 1] - tau, 0.f);
            float p2 = fmaxf(z[j + 2] - tau, 0.f);
            float p3 = fmaxf(z[j + 3] - tau, 0.f);
            a0 = fmaf(p0, p0, a0);
            a1 = fmaf(p1, p1, a1);
            a2 = fmaf(p2, p2, a2);
            a3 = fmaf(p3, p3, a3);
        }
        float sp   = qf - kf * tau;             // sum of (z'-tau') over support
        float rsum = ((a0 + a1) + (a2 + a3)) + (tau - 256.0f) * sp;

        bool valid = role ? (r < ntp) : (r < nv);
        red[tid] = valid ? rsum : 0.0f;
    }
    __syncthreads();

    // ---- Phase 4: masked means; warp 0 -> pair 0, warp 1 -> pair 1 ----
    if (tid < 64) {
        const int wp   = tid >> 5;
        const int lane = tid & 31;
        const float* rp = red + wp * 128;
        float v = rp[lane]      + rp[lane + 32];
        float w = rp[64 + lane] + rp[96 + lane];
        #pragma unroll
        for (int o = 16; o; o >>= 1) {
            v += __shfl_down_sync(0xffffffffu, v, o);
            w += __shfl_down_sync(0xffffffffu, w, o);
        }
        if (lane == 0) {
            int nt = wp ? nt1 : nt0;
            out[i * B_CAP + t0 + wp] = 0.5f * (v / (float)nv + w / (float)nt);
        }
    }
}

extern "C" void kernel_launch(void* const* d_in, const int* in_sizes, int n_in,
                              void* d_out, int out_size)
{
    // metadata order: img_cls, imgs, cap_cls, caps, img_lens, cap_lens
    const float* imgs     = (const float*)d_in[1];
    const float* caps     = (const float*)d_in[3];
    const int*   img_lens = (const int*)d_in[4];
    const int*   cap_lens = (const int*)d_in[5];
    float*       out      = (float*)d_out;

    cudaFuncSetAttribute(select_kernel,
                         cudaFuncAttributeMaxDynamicSharedMemorySize, SMEM_BYTES);

    dim3 grid(B_CAP / 2, B_IMG);
    select_kernel<<<grid, 256, SMEM_BYTES>>>(imgs, caps, img_lens, cap_lens, out);
}

// round 7
// speedup vs baseline: 1.0359x; 1.0359x over previous
#include <cuda_runtime.h>
#include <cstdint>

#define B_IMG 128
#define B_CAP 128
#define R 64
#define W 64
#define D 128

#define A_PITCH 132            // (4g + t4) distinct mod 32 -> conflict-free frag loads
#define S_PITCH 65             // stride 1 across threads -> conflict-free rows AND cols
#define TILE_F  (64 * A_PITCH) // 8448 floats per operand tile
#define SS_F    (64 * S_PITCH) // 4160 floats per sims tile (2 overlay into As: 8320<=8448)

#define SMEM_FLOATS (3 * TILE_F + 256)
#define SMEM_BYTES  (SMEM_FLOATS * 4)   // 100 KB -> 2 CTAs/SM

__device__ __forceinline__ uint32_t f2tf32(float x) {
    uint32_t r;
    asm("cvt.rna.tf32.f32 %0, %1;" : "=r"(r) : "f"(x));
    return r;
}

#define MMA_TF32(d, a, b)                                                     \
    asm volatile(                                                             \
        "mma.sync.aligned.m16n8k8.row.col.f32.tf32.tf32.f32 "                 \
        "{%0,%1,%2,%3}, {%4,%5,%6,%7}, {%8,%9}, {%0,%1,%2,%3};\n"             \
        : "+f"(d[0]), "+f"(d[1]), "+f"(d[2]), "+f"(d[3])                      \
        : "r"(a[0]), "r"(a[1]), "r"(a[2]), "r"(a[3]), "r"(b[0]), "r"(b[1]))

// One CTA = 1 image x 2 captions. 512 threads.
// GEMM: warps 0-7 -> pair 0, warps 8-15 -> pair 1; each warp does 16x32.
// Sparsemax: each 64-elem line split across a lane-pair (bit0 of tid).
__global__ __launch_bounds__(512, 2) void select_kernel(
    const float* __restrict__ imgs, const float* __restrict__ caps,
    const int* __restrict__ img_lens, const int* __restrict__ cap_lens,
    float* __restrict__ out)
{
    extern __shared__ float sm[];
    float* As  = sm;                    // [64][A_PITCH] tf32 imgs tile
    float* Bs0 = sm + TILE_F;           // caps tile pair 0 (pair 1 at +TILE_F)
    float* red = sm + 3 * TILE_F;       // [256]

    const int i   = blockIdx.y;
    const int t0  = blockIdx.x * 2;
    const int tid = threadIdx.x;

    const int nv  = __ldg(img_lens + i);
    const int nt0 = __ldg(cap_lens + t0);
    const int nt1 = __ldg(cap_lens + t0 + 1);

    // ---- Phase 1: coalesced load + tf32-convert into padded smem ----
    {
        const float4* gi = (const float4*)(imgs + (size_t)i * R * D);
        const float4* gc = (const float4*)(caps + (size_t)t0 * W * D);
        #pragma unroll
        for (int j = tid; j < R * D / 4; j += 512) {
            float4 v = gi[j];
            int row = j >> 5, c4 = (j & 31) << 2;
            float4 w;
            w.x = __uint_as_float(f2tf32(v.x));
            w.y = __uint_as_float(f2tf32(v.y));
            w.z = __uint_as_float(f2tf32(v.z));
            w.w = __uint_as_float(f2tf32(v.w));
            *(float4*)(As + row * A_PITCH + c4) = w;
        }
        #pragma unroll
        for (int j = tid; j < 2 * W * D / 4; j += 512) {
            float4 v = gc[j];
            int p = j >> 11;
            int jj = j & 2047;
            int row = jj >> 5, c4 = (jj & 31) << 2;
            float4 w;
            w.x = __uint_as_float(f2tf32(v.x));
            w.y = __uint_as_float(f2tf32(v.y));
            w.z = __uint_as_float(f2tf32(v.z));
            w.w = __uint_as_float(f2tf32(v.w));
            *(float4*)(Bs0 + p * TILE_F + row * A_PITCH + c4) = w;
        }
    }
    __syncthreads();

    // ---- Phase 2: per pair 64x64x128 GEMM, 8 warps/pair, 16x32 per warp ----
    {
        const int warp = tid >> 5;
        const int lane = tid & 31;
        const int p    = warp >> 3;        // pair
        const int w8   = warp & 7;
        const int g    = lane >> 2;
        const int t4   = lane & 3;
        const int warpM = (w8 & 3) * 16;
        const int warpN = (w8 >> 2) * 32;
        const float* Bp = Bs0 + p * TILE_F;
        const int   ntp = p ? nt1 : nt0;

        float acc[4][4];
        #pragma unroll
        for (int ni = 0; ni < 4; ++ni)
            #pragma unroll
            for (int q = 0; q < 4; ++q) acc[ni][q] = 0.0f;

        #pragma unroll
        for (int kk = 0; kk < D; kk += 8) {
            uint32_t a[4], b[4][2];
            const float* ap = As + (warpM + g) * A_PITCH + kk + t4;
            a[0] = __float_as_uint(ap[0]);
            a[1] = __float_as_uint(ap[8 * A_PITCH]);
            a[2] = __float_as_uint(ap[4]);
            a[3] = __float_as_uint(ap[8 * A_PITCH + 4]);
            #pragma unroll
            for (int ni = 0; ni < 4; ++ni) {
                const float* bp = Bp + (warpN + ni * 8 + g) * A_PITCH + kk + t4;
                b[ni][0] = __float_as_uint(bp[0]);
                b[ni][1] = __float_as_uint(bp[4]);
            }
            #pragma unroll
            for (int ni = 0; ni < 4; ++ni)
                MMA_TF32(acc[ni], a, b[ni]);
        }

        __syncthreads();   // all warps done reading As/Bs; Ss overlays As

        // epilogue: store PRE-SHIFTED sims z' = sims + 256 (masked -> exactly 255)
        float* Sp = sm + p * SS_F;
        #pragma unroll
        for (int ni = 0; ni < 4; ++ni) {
            int r0 = warpM + g;
            int r1 = r0 + 8;
            int c0 = warpN + ni * 8 + 2 * t4;
            bool cv0 = (c0 < ntp), cv1 = (c0 + 1 < ntp);
            Sp[r0 * S_PITCH + c0]     = (r0 < nv && cv0) ? acc[ni][0] + 256.0f : 255.0f;
            Sp[r0 * S_PITCH + c0 + 1] = (r0 < nv && cv1) ? acc[ni][1] + 256.0f : 255.0f;
            Sp[r1 * S_PITCH + c0]     = (r1 < nv && cv0) ? acc[ni][2] + 256.0f : 255.0f;
            Sp[r1 * S_PITCH + c0 + 1] = (r1 < nv && cv1) ? acc[ni][3] + 256.0f : 255.0f;
        }
    }
    __syncthreads();

    // ---- Phase 3: sparsemax, lane-pair split, shifted-accumulator Michelot ----
    // tid layout: [pair(1)][role(1)][line(6)][half(1)]
    {
        const int p    = tid >> 8;
        const int role = (tid >> 7) & 1;
        const int line = (tid >> 1) & 63;
        const int half = tid & 1;
        const int lane = tid & 31;
        const unsigned pmask = 0x3u << (lane & 30);   // this lane-pair

        const float* Sp = sm + p * SS_F;
        const int   ntp = p ? nt1 : nt0;
        const int   m   = role ? nv : ntp;      // valid elements in this line

        const float* bp;
        int str;
        if (role == 0) { bp = Sp + line * S_PITCH + half * 32; str = 1; }
        else           { bp = Sp + (half * 32) * S_PITCH + line; str = S_PITCH; }

        float z[32];
        #pragma unroll
        for (int j = 0; j < 32; ++j) z[j] = bp[j * str];

        // line sum via pair combine
        float s0 = 0.f, s1 = 0.f, s2 = 0.f, s3 = 0.f;
        #pragma unroll
        for (int j = 0; j < 32; j += 4) {
            s0 += z[j]; s1 += z[j + 1]; s2 += z[j + 2]; s3 += z[j + 3];
        }
        float Sloc = (s0 + s1) + (s2 + s3);
        float S = Sloc + __shfl_xor_sync(pmask, Sloc, 1);

        // analytic init: support = valid set (masked entries sit at exactly 255)
        float kprev = (float)m;
        float tau = __fdividef(S - (float)(64 - m) * 255.0f - 1.0f, kprev);
        if (!(tau > 255.0f)) {                  // rare: true support includes masked
            tau = (S - 1.0f) * (1.0f / 64.0f);
            kprev = 64.0f;
        }

        // Michelot with joint sum+count accumulator: q = sum + 256*count
        float qf = kprev * tau + 1.0f;          // consistent q for the init tau
        float kf = kprev;
        #pragma unroll 1
        for (int it = 0; it < 24; ++it) {
            float q0 = 0.f, q1 = 0.f, q2 = 0.f, q3 = 0.f;
            #pragma unroll
            for (int j = 0; j < 32; j += 4) {
                if (z[j]     > tau) q0 += z[j];
                if (z[j + 1] > tau) q1 += z[j + 1];
                if (z[j + 2] > tau) q2 += z[j + 2];
                if (z[j + 3] > tau) q3 += z[j + 3];
            }
            float qloc = (q0 + q1) + (q2 + q3);
            qf = qloc + __shfl_xor_sync(pmask, qloc, 1);  // identical on both halves
            kf = rintf(qf * 0.00390625f);       // exact count: |sum sims| <= 64 < 128
            if (kf == kprev) break;             // support stable -> tau is the fixpoint
            kprev = kf;
            tau = __fdividef(qf - 1.0f, kf);
        }

        // rsum = sum_active (z - tau)*z  [unshifted]
        //      = sum relu(z'-tau')^2 + (tau'-256) * sum relu(z'-tau')
        float a0 = 0.f, a1 = 0.f, a2 = 0.f, a3 = 0.f;
        #pragma unroll
        for (int j = 0; j < 32; j += 4) {
            float p0 = fmaxf(z[j]     - tau, 0.f);
            float p1 = fmaxf(z[j + 1] - tau, 0.f);
            float p2 = fmaxf(z[j + 2] - tau, 0.f);
            float p3 = fmaxf(z[j + 3] - tau, 0.f);
            a0 = fmaf(p0, p0, a0);
            a1 = fmaf(p1, p1, a1);
            a2 = fmaf(p2, p2, a2);
            a3 = fmaf(p3, p3, a3);
        }
        float aloc = (a0 + a1) + (a2 + a3);
        float atot = aloc + __shfl_xor_sync(pmask, aloc, 1);
        float sp   = qf - kf * tau;             // sum of (z'-tau') over support
        float rsum = atot + (tau - 256.0f) * sp;

        bool valid = role ? (line < ntp) : (line < nv);
        if (half == 0)
            red[p * 128 + role * 64 + line] = valid ? rsum : 0.0f;
    }
    __syncthreads();

    // ---- Phase 4: masked means; warp 0 -> pair 0, warp 1 -> pair 1 ----
    if (tid < 64) {
        const int wp   = tid >> 5;
        const int lane = tid & 31;
        const float* rp = red + wp * 128;
        float v = rp[lane]      + rp[lane + 32];
        float w = rp[64 + lane] + rp[96 + lane];
        #pragma unroll
        for (int o = 16; o; o >>= 1) {
            v += __shfl_down_sync(0xffffffffu, v, o);
            w += __shfl_down_sync(0xffffffffu, w, o);
        }
        if (lane == 0) {
            int nt = wp ? nt1 : nt0;
            out[i * B_CAP + t0 + wp] = 0.5f * (v / (float)nv + w / (float)nt);
        }
    }
}

extern "C" void kernel_launch(void* const* d_in, const int* in_sizes, int n_in,
                              void* d_out, int out_size)
{
    // metadata order: img_cls, imgs, cap_cls, caps, img_lens, cap_lens
    const float* imgs     = (const float*)d_in[1];
    const float* caps     = (const float*)d_in[3];
    const int*   img_lens = (const int*)d_in[4];
    const int*   cap_lens = (const int*)d_in[5];
    float*       out      = (float*)d_out;

    cudaFuncSetAttribute(select_kernel,
                         cudaFuncAttributeMaxDynamicSharedMemorySize, SMEM_BYTES);

    dim3 grid(B_CAP / 2, B_IMG);
    select_kernel<<<grid, 512, SMEM_BYTES>>>(imgs, caps, img_lens, cap_lens, out);
}

// round 9
// speedup vs baseline: 1.7193x; 1.6596x over previous
#include <cuda_runtime.h>
#include <cuda_bf16.h>
#include <cstdint>

#define B_IMG 128
#define B_CAP 128
#define R 64
#define W 64
#define D 128

// Operand tiles: bf16 pairs packed in u32. 64 u32 per row (D=128), pitch 68:
// 68 mod 32 = 4 -> frag address (4g + t4) distinct mod 32 -> conflict-free.
#define OP_PITCH 68
#define OP_TILE  (64 * OP_PITCH)     // 4352 u32 per operand tile
#define S_PITCH  65                  // sims: stride 1 across threads -> conflict-free
#define SS_F     (64 * S_PITCH)      // 4160 floats; 2 tiles (8320) overlay operands (13056)

#define SMEM_U32  (3 * OP_TILE + 256)
#define SMEM_BYTES (SMEM_U32 * 4)    // 53,248 B

__device__ __forceinline__ uint32_t pack_bf16x2(float lo, float hi) {
    __nv_bfloat162 h = __float22bfloat162_rn(make_float2(lo, hi)); // .x = low half
    return *(uint32_t*)&h;
}

#define MMA_BF16(d, a, b)                                                     \
    asm volatile(                                                             \
        "mma.sync.aligned.m16n8k16.row.col.f32.bf16.bf16.f32 "                \
        "{%0,%1,%2,%3}, {%4,%5,%6,%7}, {%8,%9}, {%0,%1,%2,%3};\n"             \
        : "+f"(d[0]), "+f"(d[1]), "+f"(d[2]), "+f"(d[3])                      \
        : "r"(a[0]), "r"(a[1]), "r"(a[2]), "r"(a[3]), "r"(b[0]), "r"(b[1]))

// One CTA = 1 image x 2 captions. 256 threads.
// Warps 0-3 -> pair 0 GEMM, warps 4-7 -> pair 1 GEMM (each warp 32x32 of 64x64).
__global__ __launch_bounds__(256) void select_kernel(
    const float* __restrict__ imgs, const float* __restrict__ caps,
    const int* __restrict__ img_lens, const int* __restrict__ cap_lens,
    float* __restrict__ out)
{
    extern __shared__ uint32_t smu[];
    float* smf = (float*)smu;
    uint32_t* As  = smu;                 // [64][OP_PITCH] bf16x2 imgs tile
    uint32_t* Bs0 = smu + OP_TILE;       // caps tile pair 0 (pair 1 at +OP_TILE)
    float*    red = smf + 3 * OP_TILE;   // [256]

    const int i   = blockIdx.y;
    const int t0  = blockIdx.x * 2;
    const int tid = threadIdx.x;

    const int nv  = __ldg(img_lens + i);
    const int nt0 = __ldg(cap_lens + t0);
    const int nt1 = __ldg(cap_lens + t0 + 1);

    // ---- Phase 1: coalesced float4 load -> bf16x2 pack -> padded smem ----
    {
        const float4* gi = (const float4*)(imgs + (size_t)i * R * D);
        const float4* gc = (const float4*)(caps + (size_t)t0 * W * D);
        #pragma unroll
        for (int j = tid; j < R * D / 4; j += 256) {
            float4 v = gi[j];
            int row = j >> 5, cu = (j & 31) << 1;      // u32 column
            uint2 w;
            w.x = pack_bf16x2(v.x, v.y);
            w.y = pack_bf16x2(v.z, v.w);
            *(uint2*)(As + row * OP_PITCH + cu) = w;
        }
        #pragma unroll
        for (int j = tid; j < 2 * W * D / 4; j += 256) {
            float4 v = gc[j];
            int p = j >> 11;
            int jj = j & 2047;
            int row = jj >> 5, cu = (jj & 31) << 1;
            uint2 w;
            w.x = pack_bf16x2(v.x, v.y);
            w.y = pack_bf16x2(v.z, v.w);
            *(uint2*)(Bs0 + p * OP_TILE + row * OP_PITCH + cu) = w;
        }
    }
    __syncthreads();

    // ---- Phase 2: per pair 64x64x128 GEMM via m16n8k16 bf16 mma ----
    {
        const int warp = tid >> 5;
        const int lane = tid & 31;
        const int p    = warp >> 2;
        const int w4   = warp & 3;
        const int g    = lane >> 2;
        const int t4   = lane & 3;
        const int warpM = (w4 >> 1) * 32;
        const int warpN = (w4 & 1) * 32;
        const uint32_t* Bp = Bs0 + p * OP_TILE;
        const int   ntp = p ? nt1 : nt0;

        float acc[2][4][4];
        #pragma unroll
        for (int mi = 0; mi < 2; ++mi)
            #pragma unroll
            for (int ni = 0; ni < 4; ++ni)
                #pragma unroll
                for (int q = 0; q < 4; ++q) acc[mi][ni][q] = 0.0f;

        #pragma unroll
        for (int kb = 0; kb < 8; ++kb) {         // 8 k-blocks of 16
            const int off = kb * 8 + t4;         // u32 col: k=2t4 pair
            uint32_t a[2][4], b[4][2];
            #pragma unroll
            for (int mi = 0; mi < 2; ++mi) {
                const uint32_t* ap = As + (warpM + mi * 16 + g) * OP_PITCH + off;
                a[mi][0] = ap[0];                 // row g,   k 2t4..2t4+1
                a[mi][1] = ap[8 * OP_PITCH];      // row g+8
                a[mi][2] = ap[4];                 // row g,   k 2t4+8..+9
                a[mi][3] = ap[8 * OP_PITCH + 4];
            }
            #pragma unroll
            for (int ni = 0; ni < 4; ++ni) {
                const uint32_t* bp = Bp + (warpN + ni * 8 + g) * OP_PITCH + off;
                b[ni][0] = bp[0];
                b[ni][1] = bp[4];
            }
            #pragma unroll
            for (int mi = 0; mi < 2; ++mi)
                #pragma unroll
                for (int ni = 0; ni < 4; ++ni)
                    MMA_BF16(acc[mi][ni], a[mi], b[ni]);
        }

        __syncthreads();   // operands dead; sims tiles overlay them

        // epilogue: store PRE-SHIFTED sims z' = sims + 256 (masked -> exactly 255)
        float* Sp = smf + p * SS_F;
        #pragma unroll
        for (int mi = 0; mi < 2; ++mi) {
            #pragma unroll
            for (int ni = 0; ni < 4; ++ni) {
                int r0 = warpM + mi * 16 + g;
                int r1 = r0 + 8;
                int c0 = warpN + ni * 8 + 2 * t4;
                bool cv0 = (c0 < ntp), cv1 = (c0 + 1 < ntp);
                Sp[r0 * S_PITCH + c0]     = (r0 < nv && cv0) ? acc[mi][ni][0] + 256.0f : 255.0f;
                Sp[r0 * S_PITCH + c0 + 1] = (r0 < nv && cv1) ? acc[mi][ni][1] + 256.0f : 255.0f;
                Sp[r1 * S_PITCH + c0]     = (r1 < nv && cv0) ? acc[mi][ni][2] + 256.0f : 255.0f;
                Sp[r1 * S_PITCH + c0 + 1] = (r1 < nv && cv1) ? acc[mi][ni][3] + 256.0f : 255.0f;
            }
        }
    }
    __syncthreads();

    // ---- Phase 3: sparsemax, shifted-accumulator Michelot (z pre-shifted) ----
    // tid layout: [pair(1)][role(1)][r(6)]; role 0 = region rows, role 1 = word cols
    {
        const int p    = tid >> 7;
        const int role = (tid >> 6) & 1;
        const int r    = tid & 63;
        const float* Sp = smf + p * SS_F;
        const int   ntp = p ? nt1 : nt0;
        const int   m   = role ? nv : ntp;      // valid elements in this line

        const float* bp = role ? (Sp + r) : (Sp + r * S_PITCH);
        const int   str = role ? S_PITCH : 1;

        float z[64];
        #pragma unroll
        for (int j = 0; j < 64; ++j) z[j] = bp[j * str];

        float s0 = 0.f, s1 = 0.f, s2 = 0.f, s3 = 0.f;
        #pragma unroll
        for (int j = 0; j < 64; j += 4) {
            s0 += z[j]; s1 += z[j + 1]; s2 += z[j + 2]; s3 += z[j + 3];
        }
        const float S = (s0 + s1) + (s2 + s3);

        // analytic init: support = valid set (masked entries sit at exactly 255)
        float kprev = (float)m;
        float tau = __fdividef(S - (float)(64 - m) * 255.0f - 1.0f, kprev);
        if (!(tau > 255.0f)) {                  // rare: true support includes masked
            tau = (S - 1.0f) * (1.0f / 64.0f);
            kprev = 64.0f;
        }

        // Michelot with joint sum+count accumulator: q = sum + 256*count
        float qf = kprev * tau + 1.0f;          // consistent q for the init tau
        float kf = kprev;
        #pragma unroll 1
        for (int it = 0; it < 24; ++it) {
            float q0 = 0.f, q1 = 0.f, q2 = 0.f, q3 = 0.f;
            #pragma unroll
            for (int j = 0; j < 64; j += 4) {
                if (z[j]     > tau) q0 += z[j];
                if (z[j + 1] > tau) q1 += z[j + 1];
                if (z[j + 2] > tau) q2 += z[j + 2];
                if (z[j + 3] > tau) q3 += z[j + 3];
            }
            qf = (q0 + q1) + (q2 + q3);
            kf = rintf(qf * 0.00390625f);       // exact count: |sum sims| <= 64 < 128
            if (kf == kprev) break;             // support stable -> tau is the fixpoint
            kprev = kf;
            tau = __fdividef(qf - 1.0f, kf);
        }

        // rsum = sum_active (z - tau)*z  [unshifted]
        //      = sum relu(z'-tau')^2 + (tau'-256) * sum relu(z'-tau')
        float a0 = 0.f, a1 = 0.f, a2 = 0.f, a3 = 0.f;
        #pragma unroll
        for (int j = 0; j < 64; j += 4) {
            float p0 = fmaxf(z[j]     - tau, 0.f);
            float p1 = fmaxf(z[j + 1] - tau, 0.f);
            float p2 = fmaxf(z[j + 2] - tau, 0.f);
            float p3 = fmaxf(z[j + 3] - tau, 0.f);
            a0 = fmaf(p0, p0, a0);
            a1 = fmaf(p1, p1, a1);
            a2 = fmaf(p2, p2, a2);
            a3 = fmaf(p3, p3, a3);
        }
        float sp   = qf - kf * tau;             // sum of (z'-tau') over support
        float rsum = ((a0 + a1) + (a2 + a3)) + (tau - 256.0f) * sp;

        bool valid = role ? (r < ntp) : (r < nv);
        red[tid] = valid ? rsum : 0.0f;
    }
    __syncthreads();

    // ---- Phase 4: masked means; warp 0 -> pair 0, warp 1 -> pair 1 ----
    if (tid < 64) {
        const int wp   = tid >> 5;
        const int lane = tid & 31;
        const float* rp = red + wp * 128;
        float v = rp[lane]      + rp[lane + 32];
        float w = rp[64 + lane] + rp[96 + lane];
        #pragma unroll
        for (int o = 16; o; o >>= 1) {
            v += __shfl_down_sync(0xffffffffu, v, o);
            w += __shfl_down_sync(0xffffffffu, w, o);
        }
        if (lane == 0) {
            int nt = wp ? nt1 : nt0;
            out[i * B_CAP + t0 + wp] = 0.5f * (v / (float)nv + w / (float)nt);
        }
    }
}

extern "C" void kernel_launch(void* const* d_in, const int* in_sizes, int n_in,
                              void* d_out, int out_size)
{
    // metadata order: img_cls, imgs, cap_cls, caps, img_lens, cap_lens
    const float* imgs     = (const float*)d_in[1];
    const float* caps     = (const float*)d_in[3];
    const int*   img_lens = (const int*)d_in[4];
    const int*   cap_lens = (const int*)d_in[5];
    float*       out      = (float*)d_out;

    cudaFuncSetAttribute(select_kernel,
                         cudaFuncAttributeMaxDynamicSharedMemorySize, SMEM_BYTES);

    dim3 grid(B_CAP / 2, B_IMG);
    select_kernel<<<grid, 256, SMEM_BYTES>>>(imgs, caps, img_lens, cap_lens, out);
}

// round 10
// speedup vs baseline: 1.8424x; 1.0716x over previous
#include <cuda_runtime.h>
#include <cuda_bf16.h>
#include <cstdint>

#define B_IMG 128
#define B_CAP 128
#define R 64
#define W 64
#define D 128

// Operand tiles: bf16 pairs packed in u32. 64 u32 per row (D=128), pitch 68:
// 68 mod 32 = 4 -> frag address (4g + t4) distinct mod 32 -> conflict-free.
#define OP_PITCH 68
#define OP_TILE  (64 * OP_PITCH)     // 4352 u32 per operand tile (3 tiles = 13056)
#define S_PITCH  68                  // sims pitch: float4 row loads conflict-free
#define SS_T     (64 * S_PITCH)      // 4352 floats per sims tile
// sims: 4 tiles (row p0, row p1, T p0, T p1) = 17408 floats, overlaying operands
#define SMEM_U32   (4 * SS_T + 256)
#define SMEM_BYTES (SMEM_U32 * 4)    // 70,656 B -> 3 CTAs/SM (212 KB <= 228 KB)

__device__ __forceinline__ uint32_t pack_bf16x2(float lo, float hi) {
    __nv_bfloat162 h = __float22bfloat162_rn(make_float2(lo, hi)); // .x = low half
    return *(uint32_t*)&h;
}

#define MMA_BF16(d, a, b)                                                     \
    asm volatile(                                                             \
        "mma.sync.aligned.m16n8k16.row.col.f32.bf16.bf16.f32 "                \
        "{%0,%1,%2,%3}, {%4,%5,%6,%7}, {%8,%9}, {%0,%1,%2,%3};\n"             \
        : "+f"(d[0]), "+f"(d[1]), "+f"(d[2]), "+f"(d[3])                      \
        : "r"(a[0]), "r"(a[1]), "r"(a[2]), "r"(a[3]), "r"(b[0]), "r"(b[1]))

// One CTA = 1 image x 2 captions. 256 threads.
// Warps 0-3 -> pair 0 GEMM, warps 4-7 -> pair 1 GEMM (each warp 32x32 of 64x64).
__global__ __launch_bounds__(256, 3) void select_kernel(
    const float* __restrict__ imgs, const float* __restrict__ caps,
    const int* __restrict__ img_lens, const int* __restrict__ cap_lens,
    float* __restrict__ out)
{
    extern __shared__ uint32_t smu[];
    float* smf = (float*)smu;
    uint32_t* As  = smu;                 // [64][OP_PITCH] bf16x2 imgs tile
    uint32_t* Bs0 = smu + OP_TILE;       // caps tile pair 0 (pair 1 at +OP_TILE)
    float*    red = smf + 4 * SS_T;      // [256]

    const int i   = blockIdx.y;
    const int t0  = blockIdx.x * 2;
    const int tid = threadIdx.x;

    const int nv  = __ldg(img_lens + i);
    const int nt0 = __ldg(cap_lens + t0);
    const int nt1 = __ldg(cap_lens + t0 + 1);

    // ---- Phase 1: coalesced float4 load -> bf16x2 pack -> padded smem ----
    {
        const float4* gi = (const float4*)(imgs + (size_t)i * R * D);
        const float4* gc = (const float4*)(caps + (size_t)t0 * W * D);
        #pragma unroll
        for (int j = tid; j < R * D / 4; j += 256) {
            float4 v = gi[j];
            int row = j >> 5, cu = (j & 31) << 1;      // u32 column
            uint2 w;
            w.x = pack_bf16x2(v.x, v.y);
            w.y = pack_bf16x2(v.z, v.w);
            *(uint2*)(As + row * OP_PITCH + cu) = w;
        }
        #pragma unroll
        for (int j = tid; j < 2 * W * D / 4; j += 256) {
            float4 v = gc[j];
            int p = j >> 11;
            int jj = j & 2047;
            int row = jj >> 5, cu = (jj & 31) << 1;
            uint2 w;
            w.x = pack_bf16x2(v.x, v.y);
            w.y = pack_bf16x2(v.z, v.w);
            *(uint2*)(Bs0 + p * OP_TILE + row * OP_PITCH + cu) = w;
        }
    }
    __syncthreads();

    // ---- Phase 2: per pair 64x64x128 GEMM via m16n8k16 bf16 mma ----
    {
        const int warp = tid >> 5;
        const int lane = tid & 31;
        const int p    = warp >> 2;
        const int w4   = warp & 3;
        const int g    = lane >> 2;
        const int t4   = lane & 3;
        const int warpM = (w4 >> 1) * 32;
        const int warpN = (w4 & 1) * 32;
        const uint32_t* Bp = Bs0 + p * OP_TILE;
        const int   ntp = p ? nt1 : nt0;

        float acc[2][4][4];
        #pragma unroll
        for (int mi = 0; mi < 2; ++mi)
            #pragma unroll
            for (int ni = 0; ni < 4; ++ni)
                #pragma unroll
                for (int q = 0; q < 4; ++q) acc[mi][ni][q] = 0.0f;

        #pragma unroll
        for (int kb = 0; kb < 8; ++kb) {         // 8 k-blocks of 16
            const int off = kb * 8 + t4;         // u32 col: k=2t4 pair
            uint32_t a[2][4], b[4][2];
            #pragma unroll
            for (int mi = 0; mi < 2; ++mi) {
                const uint32_t* ap = As + (warpM + mi * 16 + g) * OP_PITCH + off;
                a[mi][0] = ap[0];                 // row g,   k 2t4..2t4+1
                a[mi][1] = ap[8 * OP_PITCH];      // row g+8
                a[mi][2] = ap[4];                 // row g,   k 2t4+8..+9
                a[mi][3] = ap[8 * OP_PITCH + 4];
            }
            #pragma unroll
            for (int ni = 0; ni < 4; ++ni) {
                const uint32_t* bp = Bp + (warpN + ni * 8 + g) * OP_PITCH + off;
                b[ni][0] = bp[0];
                b[ni][1] = bp[4];
            }
            #pragma unroll
            for (int mi = 0; mi < 2; ++mi)
                #pragma unroll
                for (int ni = 0; ni < 4; ++ni)
                    MMA_BF16(acc[mi][ni], a[mi], b[ni]);
        }

        __syncthreads();   // operands dead; sims tiles overlay them

        // epilogue: PRE-SHIFTED sims z' = sims + 256 (masked -> exactly 255),
        // stored twice: row-major (pair tile p) and transposed (tile 2+p).
        float* Sp  = smf + p * SS_T;
        float* SpT = smf + (2 + p) * SS_T;
        #pragma unroll
        for (int mi = 0; mi < 2; ++mi) {
            #pragma unroll
            for (int ni = 0; ni < 4; ++ni) {
                int r0 = warpM + mi * 16 + g;
                int r1 = r0 + 8;
                int c0 = warpN + ni * 8 + 2 * t4;
                bool cv0 = (c0 < ntp), cv1 = (c0 + 1 < ntp);
                float v00 = (r0 < nv && cv0) ? acc[mi][ni][0] + 256.0f : 255.0f;
                float v01 = (r0 < nv && cv1) ? acc[mi][ni][1] + 256.0f : 255.0f;
                float v10 = (r1 < nv && cv0) ? acc[mi][ni][2] + 256.0f : 255.0f;
                float v11 = (r1 < nv && cv1) ? acc[mi][ni][3] + 256.0f : 255.0f;
                *(float2*)(Sp + r0 * S_PITCH + c0) = make_float2(v00, v01);
                *(float2*)(Sp + r1 * S_PITCH + c0) = make_float2(v10, v11);
                SpT[c0 * S_PITCH + r0]       = v00;   // 8t4+g mod 32 distinct
                SpT[(c0 + 1) * S_PITCH + r0] = v01;
                SpT[c0 * S_PITCH + r1]       = v10;
                SpT[(c0 + 1) * S_PITCH + r1] = v11;
            }
        }
    }
    __syncthreads();

    // ---- Phase 3: sparsemax, float4 loads, uniform Michelot (no divergence) ----
    // tid layout: [pair(1)][role(1)][r(6)]; role 0 = region rows, role 1 = word cols
    {
        const int p    = tid >> 7;
        const int role = (tid >> 6) & 1;
        const int r    = tid & 63;
        const int   ntp = p ? nt1 : nt0;
        const int   m   = role ? nv : ntp;      // valid elements in this line

        const float4* bp =
            (const float4*)(smf + (role * 2 + p) * SS_T + r * S_PITCH);

        float z[64];
        #pragma unroll
        for (int j = 0; j < 16; ++j) {
            float4 v = bp[j];
            z[4 * j] = v.x; z[4 * j + 1] = v.y; z[4 * j + 2] = v.z; z[4 * j + 3] = v.w;
        }

        float s0 = 0.f, s1 = 0.f, s2 = 0.f, s3 = 0.f;
        #pragma unroll
        for (int j = 0; j < 64; j += 4) {
            s0 += z[j]; s1 += z[j + 1]; s2 += z[j + 2]; s3 += z[j + 3];
        }
        const float S = (s0 + s1) + (s2 + s3);

        // analytic init: support = valid set (masked entries sit at exactly 255)
        float kprev = (float)m;
        float tau = __fdividef(S - (float)(64 - m) * 255.0f - 1.0f, kprev);
        if (!(tau > 255.0f)) {                  // rare: true support includes masked
            tau = (S - 1.0f) * (1.0f / 64.0f);
            kprev = 64.0f;
        }

        // Michelot, joint sum+count accumulator: q = sum + 256*count.
        // Uniform loop: converged lanes recompute their (stable) fixpoint.
        float qf = kprev * tau + 1.0f;          // consistent q for the init tau
        float kf = kprev;
        #pragma unroll 1
        for (int it = 0; it < 24; ++it) {
            float q0 = 0.f, q1 = 0.f, q2 = 0.f, q3 = 0.f;
            #pragma unroll
            for (int j = 0; j < 64; j += 4) {
                if (z[j]     > tau) q0 += z[j];
                if (z[j + 1] > tau) q1 += z[j + 1];
                if (z[j + 2] > tau) q2 += z[j + 2];
                if (z[j + 3] > tau) q3 += z[j + 3];
            }
            qf = (q0 + q1) + (q2 + q3);
            kf = rintf(qf * 0.00390625f);       // exact count: |sum sims| <= 64 < 128
            bool done = (kf == kprev);
            if (__all_sync(0xffffffffu, done)) break;
            if (!done) {
                kprev = kf;
                tau = __fdividef(qf - 1.0f, kf);
            }
        }

        // rsum = sum_active (z - tau)*z  [unshifted]
        //      = sum relu(z'-tau')^2 + (tau'-256) * sum relu(z'-tau')
        float a0 = 0.f, a1 = 0.f, a2 = 0.f, a3 = 0.f;
        #pragma unroll
        for (int j = 0; j < 64; j += 4) {
            float p0 = fmaxf(z[j]     - tau, 0.f);
            float p1 = fmaxf(z[j + 1] - tau, 0.f);
            float p2 = fmaxf(z[j + 2] - tau, 0.f);
            float p3 = fmaxf(z[j + 3] - tau, 0.f);
            a0 = fmaf(p0, p0, a0);
            a1 = fmaf(p1, p1, a1);
            a2 = fmaf(p2, p2, a2);
            a3 = fmaf(p3, p3, a3);
        }
        float sp   = qf - kf * tau;             // sum of (z'-tau') over support
        float rsum = ((a0 + a1) + (a2 + a3)) + (tau - 256.0f) * sp;

        bool valid = role ? (r < ntp) : (r < nv);
        red[tid] = valid ? rsum : 0.0f;
    }
    __syncthreads();

    // ---- Phase 4: masked means; warp 0 -> pair 0, warp 1 -> pair 1 ----
    if (tid < 64) {
        const int wp   = tid >> 5;
        const int lane = tid & 31;
        const float* rp = red + wp * 128;
        float v = rp[lane]      + rp[lane + 32];
        float w = rp[64 + lane] + rp[96 + lane];
        #pragma unroll
        for (int o = 16; o; o >>= 1) {
            v += __shfl_down_sync(0xffffffffu, v, o);
            w += __shfl_down_sync(0xffffffffu, w, o);
        }
        if (lane == 0) {
            int nt = wp ? nt1 : nt0;
            out[i * B_CAP + t0 + wp] = 0.5f * (v / (float)nv + w / (float)nt);
        }
    }
}

extern "C" void kernel_launch(void* const* d_in, const int* in_sizes, int n_in,
                              void* d_out, int out_size)
{
    // metadata order: img_cls, imgs, cap_cls, caps, img_lens, cap_lens
    const float* imgs     = (const float*)d_in[1];
    const float* caps     = (const float*)d_in[3];
    const int*   img_lens = (const int*)d_in[4];
    const int*   cap_lens = (const int*)d_in[5];
    float*       out      = (float*)d_out;

    cudaFuncSetAttribute(select_kernel,
                         cudaFuncAttributeMaxDynamicSharedMemorySize, SMEM_BYTES);

    dim3 grid(B_CAP / 2, B_IMG);
    select_kernel<<<grid, 256, SMEM_BYTES>>>(imgs, caps, img_lens, cap_lens, out);
}

// round 11
// speedup vs baseline: 1.8908x; 1.0263x over previous
#include <cuda_runtime.h>
#include <cuda_bf16.h>
#include <cstdint>

#define B_IMG 128
#define B_CAP 128
#define R 64
#define W 64
#define D 128

// Operand tiles: bf16 pairs packed in u32. 64 u32 per row (D=128), pitch 68:
// row stride 68 u32 = 4 banks -> each ldmatrix 8-row phase covers banks
// 4r..4r+3, all 32 banks exactly once -> conflict-free.
#define OP_PITCH 68
#define OP_TILE  (64 * OP_PITCH)     // 4352 u32 per operand tile (3 tiles = 13056)
#define S_PITCH  68                  // sims pitch: float4 row loads conflict-free
#define SS_T     (64 * S_PITCH)      // 4352 floats per sims tile
// sims: 4 tiles (row p0, row p1, T p0, T p1) = 17408 floats, overlaying operands
#define SMEM_U32   (4 * SS_T + 256)
#define SMEM_BYTES (SMEM_U32 * 4)    // 70,656 B -> 3 CTAs/SM (212 KB <= 228 KB)

__device__ __forceinline__ uint32_t pack_bf16x2(float lo, float hi) {
    __nv_bfloat162 h = __float22bfloat162_rn(make_float2(lo, hi)); // .x = low half
    return *(uint32_t*)&h;
}

__device__ __forceinline__ uint32_t s2u(const void* p) {
    return (uint32_t)__cvta_generic_to_shared(p);
}

#define LDSM_X4(r, addr)                                                      \
    asm volatile("ldmatrix.sync.aligned.m8n8.x4.shared.b16 {%0,%1,%2,%3}, [%4];" \
        : "=r"((r)[0]), "=r"((r)[1]), "=r"((r)[2]), "=r"((r)[3]) : "r"(addr))

#define MMA_BF16(d, a, b)                                                     \
    asm volatile(                                                             \
        "mma.sync.aligned.m16n8k16.row.col.f32.bf16.bf16.f32 "                \
        "{%0,%1,%2,%3}, {%4,%5,%6,%7}, {%8,%9}, {%0,%1,%2,%3};\n"             \
        : "+f"(d[0]), "+f"(d[1]), "+f"(d[2]), "+f"(d[3])                      \
        : "r"((a)[0]), "r"((a)[1]), "r"((a)[2]), "r"((a)[3]),                 \
          "r"((b)[0]), "r"((b)[1]))

// One CTA = 1 image x 2 captions. 256 threads.
// Warps 0-3 -> pair 0 GEMM, warps 4-7 -> pair 1 GEMM (each warp 32x32 of 64x64).
__global__ __launch_bounds__(256, 3) void select_kernel(
    const float* __restrict__ imgs, const float* __restrict__ caps,
    const int* __restrict__ img_lens, const int* __restrict__ cap_lens,
    float* __restrict__ out)
{
    extern __shared__ uint32_t smu[];
    float* smf = (float*)smu;
    uint32_t* As  = smu;                 // [64][OP_PITCH] bf16x2 imgs tile
    uint32_t* Bs0 = smu + OP_TILE;       // caps tile pair 0 (pair 1 at +OP_TILE)
    float*    red = smf + 4 * SS_T;      // [256]

    const int i   = blockIdx.y;
    const int t0  = blockIdx.x * 2;
    const int tid = threadIdx.x;

    const int nv  = __ldg(img_lens + i);
    const int nt0 = __ldg(cap_lens + t0);
    const int nt1 = __ldg(cap_lens + t0 + 1);

    // ---- Phase 1: coalesced float4 load -> bf16x2 pack -> padded smem ----
    {
        const float4* gi = (const float4*)(imgs + (size_t)i * R * D);
        const float4* gc = (const float4*)(caps + (size_t)t0 * W * D);
        #pragma unroll
        for (int j = tid; j < R * D / 4; j += 256) {
            float4 v = gi[j];
            int row = j >> 5, cu = (j & 31) << 1;      // u32 column
            uint2 w;
            w.x = pack_bf16x2(v.x, v.y);
            w.y = pack_bf16x2(v.z, v.w);
            *(uint2*)(As + row * OP_PITCH + cu) = w;
        }
        #pragma unroll
        for (int j = tid; j < 2 * W * D / 4; j += 256) {
            float4 v = gc[j];
            int p = j >> 11;
            int jj = j & 2047;
            int row = jj >> 5, cu = (jj & 31) << 1;
            uint2 w;
            w.x = pack_bf16x2(v.x, v.y);
            w.y = pack_bf16x2(v.z, v.w);
            *(uint2*)(Bs0 + p * OP_TILE + row * OP_PITCH + cu) = w;
        }
    }
    __syncthreads();

    // ---- Phase 2: per pair 64x64x128 GEMM, ldmatrix.x4 fragment loads ----
    {
        const int warp = tid >> 5;
        const int lane = tid & 31;
        const int p    = warp >> 2;
        const int w4   = warp & 3;
        const int g    = lane >> 2;
        const int t4   = lane & 3;
        const int warpM = (w4 >> 1) * 32;
        const int warpN = (w4 & 1) * 32;
        const uint32_t* Bp = Bs0 + p * OP_TILE;
        const int   ntp = p ? nt1 : nt0;

        const int l7  = lane & 7;
        const int l8  = (lane >> 3) & 1;
        const int l16 = (lane >> 4) & 1;

        // A x4: M0 rows g+0..7/k0, M1 rows +8/k0, M2 rows 0..7/k+8bf16, M3 +8/k+8
        uint32_t aAddr = s2u(As + (warpM + l7 + 8 * l8) * OP_PITCH + 4 * l16);
        // B x4: M0 n+0..7/k0, M1 same n/k+8bf16, M2 n+8/k0, M3 n+8/k+8
        uint32_t bAddr = s2u(Bp + (warpN + l7 + 8 * l16) * OP_PITCH + 4 * l8);
        const uint32_t rowStep16 = 16 * OP_PITCH * 4;   // +16 rows, bytes

        float acc[2][4][4];
        #pragma unroll
        for (int mi = 0; mi < 2; ++mi)
            #pragma unroll
            for (int ni = 0; ni < 4; ++ni)
                #pragma unroll
                for (int q = 0; q < 4; ++q) acc[mi][ni][q] = 0.0f;

        #pragma unroll
        for (int kb = 0; kb < 8; ++kb) {         // 8 k-blocks of 16
            uint32_t a[2][4], b[2][4];
            LDSM_X4(a[0], aAddr + kb * 32);
            LDSM_X4(a[1], aAddr + rowStep16 + kb * 32);
            LDSM_X4(b[0], bAddr + kb * 32);
            LDSM_X4(b[1], bAddr + rowStep16 + kb * 32);
            #pragma unroll
            for (int mi = 0; mi < 2; ++mi) {
                #pragma unroll
                for (int nq = 0; nq < 2; ++nq) {
                    MMA_BF16(acc[mi][2 * nq],     a[mi], b[nq]);      // n octet 0
                    MMA_BF16(acc[mi][2 * nq + 1], a[mi], b[nq] + 2);  // n octet 1
                }
            }
        }

        __syncthreads();   // operands dead; sims tiles overlay them

        // epilogue: PRE-SHIFTED sims z' = sims + 256 (masked -> exactly 255),
        // stored twice: row-major (pair tile p) and transposed (tile 2+p).
        float* Sp  = smf + p * SS_T;
        float* SpT = smf + (2 + p) * SS_T;
        #pragma unroll
        for (int mi = 0; mi < 2; ++mi) {
            #pragma unroll
            for (int ni = 0; ni < 4; ++ni) {
                int r0 = warpM + mi * 16 + g;
                int r1 = r0 + 8;
                int c0 = warpN + ni * 8 + 2 * t4;
                bool cv0 = (c0 < ntp), cv1 = (c0 + 1 < ntp);
                float v00 = (r0 < nv && cv0) ? acc[mi][ni][0] + 256.0f : 255.0f;
                float v01 = (r0 < nv && cv1) ? acc[mi][ni][1] + 256.0f : 255.0f;
                float v10 = (r1 < nv && cv0) ? acc[mi][ni][2] + 256.0f : 255.0f;
                float v11 = (r1 < nv && cv1) ? acc[mi][ni][3] + 256.0f : 255.0f;
                *(float2*)(Sp + r0 * S_PITCH + c0) = make_float2(v00, v01);
                *(float2*)(Sp + r1 * S_PITCH + c0) = make_float2(v10, v11);
                SpT[c0 * S_PITCH + r0]       = v00;   // 8t4+g mod 32 distinct
                SpT[(c0 + 1) * S_PITCH + r0] = v01;
                SpT[c0 * S_PITCH + r1]       = v10;
                SpT[(c0 + 1) * S_PITCH + r1] = v11;
            }
        }
    }
    __syncthreads();

    // ---- Phase 3: sparsemax, float4 loads, uniform Michelot (no divergence) ----
    // tid layout: [pair(1)][role(1)][r(6)]; role 0 = region rows, role 1 = word cols
    {
        const int p    = tid >> 7;
        const int role = (tid >> 6) & 1;
        const int r    = tid & 63;
        const int   ntp = p ? nt1 : nt0;
        const int   m   = role ? nv : ntp;      // valid elements in this line

        const float4* bp =
            (const float4*)(smf + (role * 2 + p) * SS_T + r * S_PITCH);

        float z[64];
        #pragma unroll
        for (int j = 0; j < 16; ++j) {
            float4 v = bp[j];
            z[4 * j] = v.x; z[4 * j + 1] = v.y; z[4 * j + 2] = v.z; z[4 * j + 3] = v.w;
        }

        float s0 = 0.f, s1 = 0.f, s2 = 0.f, s3 = 0.f;
        #pragma unroll
        for (int j = 0; j < 64; j += 4) {
            s0 += z[j]; s1 += z[j + 1]; s2 += z[j + 2]; s3 += z[j + 3];
        }
        const float S = (s0 + s1) + (s2 + s3);

        // analytic init: support = valid set (masked entries sit at exactly 255)
        float kprev = (float)m;
        float tau = __fdividef(S - (float)(64 - m) * 255.0f - 1.0f, kprev);
        if (!(tau > 255.0f)) {                  // rare: true support includes masked
            tau = (S - 1.0f) * (1.0f / 64.0f);
            kprev = 64.0f;
        }

        // Michelot, joint sum+count accumulator: q = sum + 256*count.
        // Uniform loop: converged lanes recompute their (stable) fixpoint.
        float qf = kprev * tau + 1.0f;          // consistent q for the init tau
        float kf = kprev;
        #pragma unroll 1
        for (int it = 0; it < 24; ++it) {
            float q0 = 0.f, q1 = 0.f, q2 = 0.f, q3 = 0.f;
            #pragma unroll
            for (int j = 0; j < 64; j += 4) {
                if (z[j]     > tau) q0 += z[j];
                if (z[j + 1] > tau) q1 += z[j + 1];
                if (z[j + 2] > tau) q2 += z[j + 2];
                if (z[j + 3] > tau) q3 += z[j + 3];
            }
            qf = (q0 + q1) + (q2 + q3);
            kf = rintf(qf * 0.00390625f);       // exact count: |sum sims| <= 64 < 128
            bool done = (kf == kprev);
            if (__all_sync(0xffffffffu, done)) break;
            if (!done) {
                kprev = kf;
                tau = __fdividef(qf - 1.0f, kf);
            }
        }

        // rsum = sum_active (z - tau)*z  [unshifted]
        //      = sum relu(z'-tau')^2 + (tau'-256) * sum relu(z'-tau')
        float a0 = 0.f, a1 = 0.f, a2 = 0.f, a3 = 0.f;
        #pragma unroll
        for (int j = 0; j < 64; j += 4) {
            float p0 = fmaxf(z[j]     - tau, 0.f);
            float p1 = fmaxf(z[j + 1] - tau, 0.f);
            float p2 = fmaxf(z[j + 2] - tau, 0.f);
            float p3 = fmaxf(z[j + 3] - tau, 0.f);
            a0 = fmaf(p0, p0, a0);
            a1 = fmaf(p1, p1, a1);
            a2 = fmaf(p2, p2, a2);
            a3 = fmaf(p3, p3, a3);
        }
        float sp   = qf - kf * tau;             // sum of (z'-tau') over support
        float rsum = ((a0 + a1) + (a2 + a3)) + (tau - 256.0f) * sp;

        bool valid = role ? (r < ntp) : (r < nv);
        red[tid] = valid ? rsum : 0.0f;
    }
    __syncthreads();

    // ---- Phase 4: masked means; warp 0 -> pair 0, warp 1 -> pair 1 ----
    if (tid < 64) {
        const int wp   = tid >> 5;
        const int lane = tid & 31;
        const float* rp = red + wp * 128;
        float v = rp[lane]      + rp[lane + 32];
        float w = rp[64 + lane] + rp[96 + lane];
        #pragma unroll
        for (int o = 16; o; o >>= 1) {
            v += __shfl_down_sync(0xffffffffu, v, o);
            w += __shfl_down_sync(0xffffffffu, w, o);
        }
        if (lane == 0) {
            int nt = wp ? nt1 : nt0;
            out[i * B_CAP + t0 + wp] = 0.5f * (v / (float)nv + w / (float)nt);
        }
    }
}

extern "C" void kernel_launch(void* const* d_in, const int* in_sizes, int n_in,
                              void* d_out, int out_size)
{
    // metadata order: img_cls, imgs, cap_cls, caps, img_lens, cap_lens
    const float* imgs     = (const float*)d_in[1];
    const float* caps     = (const float*)d_in[3];
    const int*   img_lens = (const int*)d_in[4];
    const int*   cap_lens = (const int*)d_in[5];
    float*       out      = (float*)d_out;

    cudaFuncSetAttribute(select_kernel,
                         cudaFuncAttributeMaxDynamicSharedMemorySize, SMEM_BYTES);

    dim3 grid(B_CAP / 2, B_IMG);
    select_kernel<<<grid, 256, SMEM_BYTES>>>(imgs, caps, img_lens, cap_lens, out);
}

// round 12
// speedup vs baseline: 1.8993x; 1.0045x over previous
#include <cuda_runtime.h>
#include <cuda_bf16.h>
#include <cstdint>

#define B_IMG 128
#define B_CAP 128
#define R 64
#define W 64
#define D 128

// Operand tiles: bf16 pairs packed in u32. 64 u32 per row (D=128), pitch 68:
// row stride 68 u32 = 4 banks -> each ldmatrix 8-row phase covers banks
// 4r..4r+3, all 32 banks exactly once -> conflict-free.
#define OP_PITCH 68
#define OP_TILE  (64 * OP_PITCH)     // 4352 u32 per operand tile (3 tiles = 13056)
#define S_PITCH  68                  // sims pitch: float4 row loads conflict-free
#define SS_T     (64 * S_PITCH)      // 4352 floats per sims tile
// sims: 4 tiles (row p0, row p1, T p0, T p1) = 17408 floats, overlaying operands
#define SMEM_U32   (4 * SS_T + 256)
#define SMEM_BYTES (SMEM_U32 * 4)    // 70,656 B -> 3 CTAs/SM (212 KB <= 228 KB)

__device__ __forceinline__ uint32_t pack_bf16x2(float lo, float hi) {
    __nv_bfloat162 h = __float22bfloat162_rn(make_float2(lo, hi)); // .x = low half
    return *(uint32_t*)&h;
}

__device__ __forceinline__ uint32_t s2u(const void* p) {
    return (uint32_t)__cvta_generic_to_shared(p);
}

#define LDSM_X4(r, addr)                                                      \
    asm volatile("ldmatrix.sync.aligned.m8n8.x4.shared.b16 {%0,%1,%2,%3}, [%4];" \
        : "=r"((r)[0]), "=r"((r)[1]), "=r"((r)[2]), "=r"((r)[3]) : "r"(addr))

#define MMA_BF16(d, a, b)                                                     \
    asm volatile(                                                             \
        "mma.sync.aligned.m16n8k16.row.col.f32.bf16.bf16.f32 "                \
        "{%0,%1,%2,%3}, {%4,%5,%6,%7}, {%8,%9}, {%0,%1,%2,%3};\n"             \
        : "+f"(d[0]), "+f"(d[1]), "+f"(d[2]), "+f"(d[3])                      \
        : "r"((a)[0]), "r"((a)[1]), "r"((a)[2]), "r"((a)[3]),                 \
          "r"((b)[0]), "r"((b)[1]))

// One CTA = 1 image x 2 captions. 256 threads.
// Warps 0-3 -> pair 0 GEMM, warps 4-7 -> pair 1 GEMM (each warp 32x32 of 64x64).
__global__ __launch_bounds__(256, 3) void select_kernel(
    const float* __restrict__ imgs, const float* __restrict__ caps,
    const int* __restrict__ img_lens, const int* __restrict__ cap_lens,
    float* __restrict__ out)
{
    extern __shared__ uint32_t smu[];
    float* smf = (float*)smu;
    uint32_t* As  = smu;                 // [64][OP_PITCH] bf16x2 imgs tile
    uint32_t* Bs0 = smu + OP_TILE;       // caps tile pair 0 (pair 1 at +OP_TILE)
    float*    red = smf + 4 * SS_T;      // [256]

    const int i   = blockIdx.y;
    const int t0  = blockIdx.x * 2;
    const int tid = threadIdx.x;

    const int nv  = __ldg(img_lens + i);
    const int nt0 = __ldg(cap_lens + t0);
    const int nt1 = __ldg(cap_lens + t0 + 1);

    // ---- Phase 1: coalesced float4 load -> bf16x2 pack -> padded smem ----
    {
        const float4* gi = (const float4*)(imgs + (size_t)i * R * D);
        const float4* gc = (const float4*)(caps + (size_t)t0 * W * D);
        #pragma unroll
        for (int j = tid; j < R * D / 4; j += 256) {
            float4 v = gi[j];
            int row = j >> 5, cu = (j & 31) << 1;      // u32 column
            uint2 w;
            w.x = pack_bf16x2(v.x, v.y);
            w.y = pack_bf16x2(v.z, v.w);
            *(uint2*)(As + row * OP_PITCH + cu) = w;
        }
        #pragma unroll
        for (int j = tid; j < 2 * W * D / 4; j += 256) {
            float4 v = gc[j];
            int p = j >> 11;
            int jj = j & 2047;
            int row = jj >> 5, cu = (jj & 31) << 1;
            uint2 w;
            w.x = pack_bf16x2(v.x, v.y);
            w.y = pack_bf16x2(v.z, v.w);
            *(uint2*)(Bs0 + p * OP_TILE + row * OP_PITCH + cu) = w;
        }
    }
    __syncthreads();

    // ---- Phase 2: per pair 64x64x128 GEMM, ldmatrix.x4 fragment loads ----
    {
        const int warp = tid >> 5;
        const int lane = tid & 31;
        const int p    = warp >> 2;
        const int w4   = warp & 3;
        const int g    = lane >> 2;
        const int t4   = lane & 3;
        const int warpM = (w4 >> 1) * 32;
        const int warpN = (w4 & 1) * 32;
        const uint32_t* Bp = Bs0 + p * OP_TILE;
        const int   ntp = p ? nt1 : nt0;

        const int l7  = lane & 7;
        const int l8  = (lane >> 3) & 1;
        const int l16 = (lane >> 4) & 1;

        uint32_t aAddr = s2u(As + (warpM + l7 + 8 * l8) * OP_PITCH + 4 * l16);
        uint32_t bAddr = s2u(Bp + (warpN + l7 + 8 * l16) * OP_PITCH + 4 * l8);
        const uint32_t rowStep16 = 16 * OP_PITCH * 4;   // +16 rows, bytes

        float acc[2][4][4];
        #pragma unroll
        for (int mi = 0; mi < 2; ++mi)
            #pragma unroll
            for (int ni = 0; ni < 4; ++ni)
                #pragma unroll
                for (int q = 0; q < 4; ++q) acc[mi][ni][q] = 0.0f;

        #pragma unroll
        for (int kb = 0; kb < 8; ++kb) {         // 8 k-blocks of 16
            uint32_t a[2][4], b[2][4];
            LDSM_X4(a[0], aAddr + kb * 32);
            LDSM_X4(a[1], aAddr + rowStep16 + kb * 32);
            LDSM_X4(b[0], bAddr + kb * 32);
            LDSM_X4(b[1], bAddr + rowStep16 + kb * 32);
            #pragma unroll
            for (int mi = 0; mi < 2; ++mi) {
                #pragma unroll
                for (int nq = 0; nq < 2; ++nq) {
                    MMA_BF16(acc[mi][2 * nq],     a[mi], b[nq]);      // n octet 0
                    MMA_BF16(acc[mi][2 * nq + 1], a[mi], b[nq] + 2);  // n octet 1
                }
            }
        }

        __syncthreads();   // operands dead; sims tiles overlay them

        // epilogue: PRE-SHIFTED sims z' = sims + 256 (masked -> exactly 255),
        // stored twice: row-major (pair tile p) and transposed (tile 2+p).
        float* Sp  = smf + p * SS_T;
        float* SpT = smf + (2 + p) * SS_T;
        #pragma unroll
        for (int mi = 0; mi < 2; ++mi) {
            #pragma unroll
            for (int ni = 0; ni < 4; ++ni) {
                int r0 = warpM + mi * 16 + g;
                int r1 = r0 + 8;
                int c0 = warpN + ni * 8 + 2 * t4;
                bool cv0 = (c0 < ntp), cv1 = (c0 + 1 < ntp);
                float v00 = (r0 < nv && cv0) ? acc[mi][ni][0] + 256.0f : 255.0f;
                float v01 = (r0 < nv && cv1) ? acc[mi][ni][1] + 256.0f : 255.0f;
                float v10 = (r1 < nv && cv0) ? acc[mi][ni][2] + 256.0f : 255.0f;
                float v11 = (r1 < nv && cv1) ? acc[mi][ni][3] + 256.0f : 255.0f;
                *(float2*)(Sp + r0 * S_PITCH + c0) = make_float2(v00, v01);
                *(float2*)(Sp + r1 * S_PITCH + c0) = make_float2(v10, v11);
                SpT[c0 * S_PITCH + r0]       = v00;   // 8t4+g mod 32 distinct
                SpT[(c0 + 1) * S_PITCH + r0] = v01;
                SpT[c0 * S_PITCH + r1]       = v10;
                SpT[(c0 + 1) * S_PITCH + r1] = v11;
            }
        }
    }
    __syncthreads();

    // ---- Phase 3: sparsemax, moment-based init + shifted Michelot ----
    // tid layout: [pair(1)][role(1)][r(6)]; role 0 = region rows, role 1 = word cols
    {
        const int p    = tid >> 7;
        const int role = (tid >> 6) & 1;
        const int r    = tid & 63;
        const int   ntp = p ? nt1 : nt0;
        const int   m   = role ? nv : ntp;      // valid elements in this line
        const float mf  = (float)m;

        const float4* bp =
            (const float4*)(smf + (role * 2 + p) * SS_T + r * S_PITCH);

        float z[64];
        #pragma unroll
        for (int j = 0; j < 16; ++j) {
            float4 v = bp[j];
            z[4 * j] = v.x; z[4 * j + 1] = v.y; z[4 * j + 2] = v.z; z[4 * j + 3] = v.w;
        }

        // load-pass moments: S = sum z', q2c = sum (z'-255.5)^2
        float s0 = 0.f, s1 = 0.f, s2 = 0.f, s3 = 0.f;
        float w0 = 0.f, w1 = 0.f, w2 = 0.f, w3 = 0.f;
        #pragma unroll
        for (int j = 0; j < 64; j += 4) {
            float c0 = z[j]     - 255.5f;
            float c1 = z[j + 1] - 255.5f;
            float c2 = z[j + 2] - 255.5f;
            float c3 = z[j + 3] - 255.5f;
            s0 += z[j]; s1 += z[j + 1]; s2 += z[j + 2]; s3 += z[j + 3];
            w0 = fmaf(c0, c0, w0); w1 = fmaf(c1, c1, w1);
            w2 = fmaf(c2, c2, w2); w3 = fmaf(c3, c3, w3);
        }
        const float S   = (s0 + s1) + (s2 + s3);
        const float q2c = (w0 + w1) + (w2 + w3);

        // analytic lower bound (guaranteed <= tau*): full valid-support iterate
        float kprev = mf;
        float lbtau = __fdividef(S - (float)(64 - m) * 255.0f - 1.0f, mf);
        if (!(lbtau > 255.0f)) {                // rare: support includes masked
            lbtau = (S - 1.0f) * (1.0f / 64.0f);
            kprev = 64.0f;
        }

        // Gaussian-tail model init: tau0 = 255.5 + mu + a*sigma,
        // a = Ginv(1/(m*sigma)) via quadratic fit in u = -ln(m*sigma).
        {
            float sc   = S - 16320.0f - 0.5f * mf;          // sum of centered valid
            float mu   = sc * __fdividef(1.0f, mf);
            float var  = (q2c - 0.25f * (float)(64 - m)) * __fdividef(1.0f, mf)
                         - mu * mu;
            float sig  = sqrtf(fmaxf(var, 1e-8f));
            float u    = -__logf(fmaxf(mf * sig, 1e-3f));
            u = fminf(fmaxf(u, -6.0f), -0.4f);
            float a = -0.705f + u * (-0.815f + u * (-0.052f));
            a = fminf(fmaxf(a, -0.6f), 2.6f);
            float tau0 = 255.5f + mu + a * sig;
            if (tau0 > lbtau) {                 // model init beats bound
                lbtau = lbtau;                  // keep for rescue
                kprev = -5.0f;                  // force at least one scan/update
            } else {
                tau0 = lbtau;
            }
            // stash: use tau variable below
            lbtau = lbtau;                      // (kept for k==0 rescue)
            // fallthrough with tau = tau0
            // (assign outside the block)
            s0 = tau0;                          // reuse s0 as carrier
        }
        float tau = s0;

        // Michelot, joint sum+count accumulator: q = sum + 256*count.
        // Uniform loop; overshoot self-corrects (one step lands <= tau*).
        float qf = 0.0f, kf = kprev;
        #pragma unroll 1
        for (int it = 0; it < 24; ++it) {
            float q0 = 0.f, q1 = 0.f, q2 = 0.f, q3 = 0.f;
            #pragma unroll
            for (int j = 0; j < 64; j += 4) {
                if (z[j]     > tau) q0 += z[j];
                if (z[j + 1] > tau) q1 += z[j + 1];
                if (z[j + 2] > tau) q2 += z[j + 2];
                if (z[j + 3] > tau) q3 += z[j + 3];
            }
            qf = (q0 + q1) + (q2 + q3);
            kf = rintf(qf * 0.00390625f);       // exact count: |sum sims| <= 64 < 128
            bool rescue = (kf < 0.5f);          // empty support: init overshot zmax
            bool done   = !rescue && (kf == kprev);
            if (__all_sync(0xffffffffu, done)) break;
            if (!done) {
                if (rescue) { tau = lbtau; kprev = -5.0f; }
                else        { kprev = kf; tau = __fdividef(qf - 1.0f, kf); }
            }
        }

        // rsum = sum_active (z - tau)*z  [unshifted]
        //      = sum relu(z'-tau')^2 + (tau'-256) * sum relu(z'-tau')
        float a0 = 0.f, a1 = 0.f, a2 = 0.f, a3 = 0.f;
        #pragma unroll
        for (int j = 0; j < 64; j += 4) {
            float p0 = fmaxf(z[j]     - tau, 0.f);
            float p1 = fmaxf(z[j + 1] - tau, 0.f);
            float p2 = fmaxf(z[j + 2] - tau, 0.f);
            float p3 = fmaxf(z[j + 3] - tau, 0.f);
            a0 = fmaf(p0, p0, a0);
            a1 = fmaf(p1, p1, a1);
            a2 = fmaf(p2, p2, a2);
            a3 = fmaf(p3, p3, a3);
        }
        float sp   = qf - kf * tau;             // sum of (z'-tau') over support
        float rsum = ((a0 + a1) + (a2 + a3)) + (tau - 256.0f) * sp;

        bool valid = role ? (r < ntp) : (r < nv);
        red[tid] = valid ? rsum : 0.0f;
    }
    __syncthreads();

    // ---- Phase 4: masked means; warp 0 -> pair 0, warp 1 -> pair 1 ----
    if (tid < 64) {
        const int wp   = tid >> 5;
        const int lane = tid & 31;
        const float* rp = red + wp * 128;
        float v = rp[lane]      + rp[lane + 32];
        float w = rp[64 + lane] + rp[96 + lane];
        #pragma unroll
        for (int o = 16; o; o >>= 1) {
            v += __shfl_down_sync(0xffffffffu, v, o);
            w += __shfl_down_sync(0xffffffffu, w, o);
        }
        if (lane == 0) {
            int nt = wp ? nt1 : nt0;
            out[i * B_CAP + t0 + wp] = 0.5f * (v / (float)nv + w / (float)nt);
        }
    }
}

extern "C" void kernel_launch(void* const* d_in, const int* in_sizes, int n_in,
                              void* d_out, int out_size)
{
    // metadata order: img_cls, imgs, cap_cls, caps, img_lens, cap_lens
    const float* imgs     = (const float*)d_in[1];
    const float* caps     = (const float*)d_in[3];
    const int*   img_lens = (const int*)d_in[4];
    const int*   cap_lens = (const int*)d_in[5];
    float*       out      = (float*)d_out;

    cudaFuncSetAttribute(select_kernel,
                         cudaFuncAttributeMaxDynamicSharedMemorySize, SMEM_BYTES);

    dim3 grid(B_CAP / 2, B_IMG);
    select_kernel<<<grid, 256, SMEM_BYTES>>>(imgs, caps, img_lens, cap_lens, out);
}